// round 1
// baseline (speedup 1.0000x reference)
#include <cuda_runtime.h>
#include <math.h>

// ---------------------------------------------------------------------------
// AttentionHead: out = softmax((q Wq^T)(k Wk^T)^T / sqrt(D)) (v Wv^T)
// B=4, S=2048, D=1024.  fp32 baseline, SIMT tiled SGEMM.
// ---------------------------------------------------------------------------

#define B_ 4
#define S_ 2048
#define D_ 1024

// Scratch: __device__ globals (no allocation allowed in kernel_launch).
__device__ float g_qp[(size_t)B_ * S_ * D_];   // 33.5 MB
__device__ float g_kp[(size_t)B_ * S_ * D_];
__device__ float g_vp[(size_t)B_ * S_ * D_];
__device__ float g_s [(size_t)B_ * S_ * S_];   // 67 MB

constexpr int BM = 128, BN = 128, BK = 16, TM = 8, TN = 8;
constexpr int NTHREADS = 256;

// Load a BMx BK tile from a K-contiguous (row-major [rows, K]) matrix,
// transposed into smem layout Xs[k][m].
__device__ __forceinline__ void load_kmajor_tile(
    const float* __restrict__ X, size_t ldk, int rowbase, int k0,
    float Xs[BK][BM + 4], int tid)
{
    int r  = tid >> 2;          // 0..63
    int c4 = (tid & 3) << 2;    // 0,4,8,12
    const float4 v0 = *(const float4*)(X + (size_t)(rowbase + r)      * ldk + k0 + c4);
    const float4 v1 = *(const float4*)(X + (size_t)(rowbase + r + 64) * ldk + k0 + c4);
    Xs[c4 + 0][r]      = v0.x; Xs[c4 + 1][r]      = v0.y;
    Xs[c4 + 2][r]      = v0.z; Xs[c4 + 3][r]      = v0.w;
    Xs[c4 + 0][r + 64] = v1.x; Xs[c4 + 1][r + 64] = v1.y;
    Xs[c4 + 2][r + 64] = v1.z; Xs[c4 + 3][r + 64] = v1.w;
}

// C[M,N] = scale * A * op(B)
//   TRANSB=true : C[m,n] = sum_k A[m,k] * B[n,k]   (A:[M,K], B:[N,K], both K-contig)
//   TRANSB=false: C[m,n] = sum_k A[m,k] * B[k,n]   (A:[M,K], B:[K,N])
// Batched via blockIdx.z with element strides sA/sB/sC.
template <bool TRANSB>
__global__ __launch_bounds__(NTHREADS)
void sgemm_kernel(const float* __restrict__ A, const float* __restrict__ B,
                  float* __restrict__ C,
                  int M, int N, int K,
                  size_t sA, size_t sB, size_t sC, float scale)
{
    __shared__ float As[BK][BM + 4];
    __shared__ float Bs[BK][BN + 4];

    A += (size_t)blockIdx.z * sA;
    B += (size_t)blockIdx.z * sB;
    C += (size_t)blockIdx.z * sC;

    const int bm = blockIdx.y * BM;
    const int bn = blockIdx.x * BN;
    const int tid = threadIdx.x;
    const int tx = tid & 15;        // 0..15 -> N
    const int ty = tid >> 4;        // 0..15 -> M

    float acc[TM][TN];
#pragma unroll
    for (int i = 0; i < TM; i++)
#pragma unroll
        for (int j = 0; j < TN; j++) acc[i][j] = 0.f;

    for (int k0 = 0; k0 < K; k0 += BK) {
        load_kmajor_tile(A, (size_t)K, bm, k0, As, tid);
        if (TRANSB) {
            load_kmajor_tile(B, (size_t)K, bn, k0, Bs, tid);
        } else {
            // B is [K,N] row-major: tile rows k0..k0+15, cols bn..bn+127.
            int kr  = tid >> 5;          // 0..7
            int c4  = (tid & 31) << 2;   // 0..124
            const float4 b0 = *(const float4*)(B + (size_t)(k0 + kr)     * N + bn + c4);
            const float4 b1 = *(const float4*)(B + (size_t)(k0 + kr + 8) * N + bn + c4);
            *(float4*)&Bs[kr][c4]     = b0;
            *(float4*)&Bs[kr + 8][c4] = b1;
        }
        __syncthreads();

#pragma unroll
        for (int kk = 0; kk < BK; kk++) {
            float a[TM], b[TN];
            *(float4*)&a[0] = *(const float4*)&As[kk][ty * TM];
            *(float4*)&a[4] = *(const float4*)&As[kk][ty * TM + 4];
            *(float4*)&b[0] = *(const float4*)&Bs[kk][tx * TN];
            *(float4*)&b[4] = *(const float4*)&Bs[kk][tx * TN + 4];
#pragma unroll
            for (int i = 0; i < TM; i++)
#pragma unroll
                for (int j = 0; j < TN; j++)
                    acc[i][j] = fmaf(a[i], b[j], acc[i][j]);
        }
        __syncthreads();
    }

#pragma unroll
    for (int i = 0; i < TM; i++) {
        const size_t row = (size_t)(bm + ty * TM + i);
        float4 o0, o1;
        o0.x = acc[i][0] * scale; o0.y = acc[i][1] * scale;
        o0.z = acc[i][2] * scale; o0.w = acc[i][3] * scale;
        o1.x = acc[i][4] * scale; o1.y = acc[i][5] * scale;
        o1.z = acc[i][6] * scale; o1.w = acc[i][7] * scale;
        *(float4*)(C + row * N + bn + tx * TN)     = o0;
        *(float4*)(C + row * N + bn + tx * TN + 4) = o1;
    }
}

// Row-wise softmax WITHOUT max-subtraction (matches reference exp/sum; scores
// are ~N(0,1) so exp never overflows). In place over g_s.
// One block (256 threads) per row of 2048 elements.
__global__ __launch_bounds__(256)
void softmax_rows_kernel(float* __restrict__ S, int n)
{
    const size_t row = blockIdx.x;
    float* s = S + row * (size_t)n;
    const int t = threadIdx.x;

    float vals[8];
    float local = 0.f;
#pragma unroll
    for (int i = 0; i < 8; i++) {
        float v = expf(s[t + i * 256]);
        vals[i] = v;
        local += v;
    }

    __shared__ float red[256];
    red[t] = local;
    __syncthreads();
#pragma unroll
    for (int off = 128; off > 0; off >>= 1) {
        if (t < off) red[t] += red[t + off];
        __syncthreads();
    }
    const float inv = 1.f / red[0];
#pragma unroll
    for (int i = 0; i < 8; i++)
        s[t + i * 256] = vals[i] * inv;
}

extern "C" void kernel_launch(void* const* d_in, const int* in_sizes, int n_in,
                              void* d_out, int out_size)
{
    const float* q  = (const float*)d_in[0];
    const float* k  = (const float*)d_in[1];
    const float* v  = (const float*)d_in[2];
    const float* wq = (const float*)d_in[3];
    const float* wk = (const float*)d_in[4];
    const float* wv = (const float*)d_in[5];
    float* out = (float*)d_out;

    float *qp, *kp, *vp, *sbuf;
    cudaGetSymbolAddress((void**)&qp,   g_qp);
    cudaGetSymbolAddress((void**)&kp,   g_kp);
    cudaGetSymbolAddress((void**)&vp,   g_vp);
    cudaGetSymbolAddress((void**)&sbuf, g_s);

    const int MS = B_ * S_;              // 8192 rows for projections
    const float inv_sqrt_d = 1.f / 32.f; // 1/sqrt(1024)

    // 1) Projections: xp = x @ W^T  (NT GEMM, M=8192, N=1024, K=1024)
    dim3 gproj(D_ / BN, MS / BM, 1);
    sgemm_kernel<true><<<gproj, NTHREADS>>>(q, wq, qp, MS, D_, D_, 0, 0, 0, 1.f);
    sgemm_kernel<true><<<gproj, NTHREADS>>>(k, wk, kp, MS, D_, D_, 0, 0, 0, 1.f);
    sgemm_kernel<true><<<gproj, NTHREADS>>>(v, wv, vp, MS, D_, D_, 0, 0, 0, 1.f);

    // 2) Scores: S[b,i,j] = (qp[b,i] . kp[b,j]) / 32   (batched NT GEMM)
    dim3 gsc(S_ / BN, S_ / BM, B_);
    sgemm_kernel<true><<<gsc, NTHREADS>>>(qp, kp, sbuf, S_, S_, D_,
                                          (size_t)S_ * D_, (size_t)S_ * D_,
                                          (size_t)S_ * S_, inv_sqrt_d);

    // 3) Softmax rows (in place)
    softmax_rows_kernel<<<B_ * S_, 256>>>(sbuf, S_);

    // 4) Output: out[b,i,d] = P[b,i,:] @ vp[b,:,d]  (batched NN GEMM)
    dim3 gout(D_ / BN, S_ / BM, B_);
    sgemm_kernel<false><<<gout, NTHREADS>>>(sbuf, vp, out, S_, D_, S_,
                                            (size_t)S_ * S_, (size_t)S_ * D_,
                                            (size_t)S_ * D_, 1.f);
}

// round 2
// speedup vs baseline: 2.8562x; 2.8562x over previous
#include <cuda_runtime.h>
#include <math.h>

// ---------------------------------------------------------------------------
// AttentionHead: out = softmax((q Wq^T)(k Wk^T)^T / sqrt(D)) (v Wv^T)
// B=4, S=2048, D=1024.  TF32 tensor-core GEMMs (mma.sync.m16n8k8).
// ---------------------------------------------------------------------------

#define B_ 4
#define S_ 2048
#define D_ 1024

__device__ float g_qp[(size_t)B_ * S_ * D_];
__device__ float g_kp[(size_t)B_ * S_ * D_];
__device__ float g_vp[(size_t)B_ * S_ * D_];
__device__ float g_s [(size_t)B_ * S_ * S_];

constexpr int BM = 128, BN = 128, BK = 32;
constexpr int ALD = 36;           // smem lda: bank = (36*g + t) % 32 = 4g+t = lane (conflict-free)
constexpr int ASZ = BM * ALD;     // floats per A stage
constexpr int NLD = 132;          // [k][n] layout lda for NN case: bank = 4t+g (conflict-free)

__device__ __forceinline__ void cp16(float* dst, const float* src) {
    unsigned d = (unsigned)__cvta_generic_to_shared(dst);
    asm volatile("cp.async.cg.shared.global [%0], [%1], 16;\n" :: "r"(d), "l"(src));
}
__device__ __forceinline__ void cp_commit() { asm volatile("cp.async.commit_group;\n"); }
template <int N> __device__ __forceinline__ void cp_wait() {
    asm volatile("cp.async.wait_group %0;\n" :: "n"(N));
}
__device__ __forceinline__ unsigned f2tf(float x) {
    unsigned r; asm("cvt.rna.tf32.f32 %0, %1;" : "=r"(r) : "f"(x)); return r;
}
__device__ __forceinline__ void mma_tf32(float* d,
    unsigned a0, unsigned a1, unsigned a2, unsigned a3, unsigned b0, unsigned b1) {
    asm volatile(
        "mma.sync.aligned.m16n8k8.row.col.f32.tf32.tf32.f32 "
        "{%0,%1,%2,%3}, {%4,%5,%6,%7}, {%8,%9}, {%0,%1,%2,%3};\n"
        : "+f"(d[0]), "+f"(d[1]), "+f"(d[2]), "+f"(d[3])
        : "r"(a0), "r"(a1), "r"(a2), "r"(a3), "r"(b0), "r"(b1));
}

// K-contiguous [rows,K] tile -> smem [row][ALD]
__device__ __forceinline__ void fill_kmajor(float* dst, const float* src, size_t ldk,
                                            int rowbase, int k0, int tid) {
    int row = tid >> 3;   // 0..31
    int ch  = tid & 7;    // 0..7  (16B chunks across 32 floats)
#pragma unroll
    for (int p = 0; p < 4; p++) {
        int r = row + p * 32;
        cp16(dst + r * ALD + ch * 4, src + (size_t)(rowbase + r) * ldk + k0 + ch * 4);
    }
}
// [K,N] row-major tile -> smem [k][NLD]
__device__ __forceinline__ void fill_nmajor(float* dst, const float* src, size_t ldn,
                                            int colbase, int k0, int tid) {
    int kr = tid >> 5;    // 0..7
    int ch = tid & 31;    // 0..31 (16B chunks across 128 floats)
#pragma unroll
    for (int p = 0; p < 4; p++) {
        int r = kr + p * 8;
        cp16(dst + r * NLD + ch * 4, src + (size_t)(k0 + r) * ldn + colbase + ch * 4);
    }
}

// C[M,N] = scale * A * op(B); TRANSB=true: B [N,K] K-contig; false: B [K,N].
template <bool TRANSB>
__global__ __launch_bounds__(256, 2)
void mma_gemm(const float* __restrict__ A, const float* __restrict__ B,
              float* __restrict__ C, int M, int N, int K,
              size_t sA, size_t sB, size_t sC, float scale)
{
    extern __shared__ float smem[];
    constexpr int BSZ = TRANSB ? BM * ALD : BK * NLD;
    float* Asm[2] = { smem, smem + ASZ };
    float* Bsm[2] = { smem + 2 * ASZ, smem + 2 * ASZ + BSZ };

    A += (size_t)blockIdx.z * sA;
    B += (size_t)blockIdx.z * sB;
    C += (size_t)blockIdx.z * sC;
    const int bm = blockIdx.y * BM, bn = blockIdx.x * BN;
    const int tid = threadIdx.x;
    const int wid = tid >> 5, lane = tid & 31;
    const int wm = wid >> 1, wn = wid & 1;   // 4 x 2 warp grid; warp tile 32x64
    const int g = lane >> 2, t = lane & 3;

    float acc[2][8][4];
#pragma unroll
    for (int i = 0; i < 2; i++)
#pragma unroll
        for (int j = 0; j < 8; j++)
#pragma unroll
            for (int r = 0; r < 4; r++) acc[i][j][r] = 0.f;

    // prologue: stage 0
    fill_kmajor(Asm[0], A, (size_t)K, bm, 0, tid);
    if (TRANSB) fill_kmajor(Bsm[0], B, (size_t)K, bn, 0, tid);
    else        fill_nmajor(Bsm[0], B, (size_t)N, bn, 0, tid);
    cp_commit();

    const int NTILES = K / BK;
    for (int kt = 0; kt < NTILES; kt++) {
        const int cur = kt & 1;
        if (kt + 1 < NTILES) {
            const int nxt = cur ^ 1;
            fill_kmajor(Asm[nxt], A, (size_t)K, bm, (kt + 1) * BK, tid);
            if (TRANSB) fill_kmajor(Bsm[nxt], B, (size_t)K, bn, (kt + 1) * BK, tid);
            else        fill_nmajor(Bsm[nxt], B, (size_t)N, bn, (kt + 1) * BK, tid);
            cp_commit();
            cp_wait<1>();
        } else {
            cp_wait<0>();
        }
        __syncthreads();

        const float* as = Asm[cur];
        const float* bs = Bsm[cur];
#pragma unroll
        for (int kk = 0; kk < 4; kk++) {
            unsigned bf[8][2];
#pragma unroll
            for (int nt = 0; nt < 8; nt++) {
                const int cb = wn * 64 + nt * 8 + g;
                if (TRANSB) {
                    bf[nt][0] = f2tf(bs[cb * ALD + kk * 8 + t]);
                    bf[nt][1] = f2tf(bs[cb * ALD + kk * 8 + t + 4]);
                } else {
                    bf[nt][0] = f2tf(bs[(kk * 8 + t) * NLD + cb]);
                    bf[nt][1] = f2tf(bs[(kk * 8 + t + 4) * NLD + cb]);
                }
            }
#pragma unroll
            for (int mt = 0; mt < 2; mt++) {
                const int rb = wm * 32 + mt * 16;
                unsigned a0 = f2tf(as[(rb + g)     * ALD + kk * 8 + t]);
                unsigned a1 = f2tf(as[(rb + g + 8) * ALD + kk * 8 + t]);
                unsigned a2 = f2tf(as[(rb + g)     * ALD + kk * 8 + t + 4]);
                unsigned a3 = f2tf(as[(rb + g + 8) * ALD + kk * 8 + t + 4]);
#pragma unroll
                for (int nt = 0; nt < 8; nt++)
                    mma_tf32(acc[mt][nt], a0, a1, a2, a3, bf[nt][0], bf[nt][1]);
            }
        }
        __syncthreads();
    }

    // epilogue
#pragma unroll
    for (int mt = 0; mt < 2; mt++) {
#pragma unroll
        for (int nt = 0; nt < 8; nt++) {
            const int row0 = bm + wm * 32 + mt * 16 + g;
            const int col  = bn + wn * 64 + nt * 8 + 2 * t;
            float2 v0 = { acc[mt][nt][0] * scale, acc[mt][nt][1] * scale };
            float2 v1 = { acc[mt][nt][2] * scale, acc[mt][nt][3] * scale };
            *(float2*)(C + (size_t)row0 * N + col)       = v0;
            *(float2*)(C + (size_t)(row0 + 8) * N + col) = v1;
        }
    }
}

// Row softmax without max-shift (matches reference); in place, one block/row.
__global__ __launch_bounds__(256)
void softmax_rows_kernel(float* __restrict__ S, int n)
{
    const size_t row = blockIdx.x;
    float* s = S + row * (size_t)n;
    const int tt = threadIdx.x;

    float vals[8];
    float local = 0.f;
#pragma unroll
    for (int i = 0; i < 8; i++) {
        float v = expf(s[tt + i * 256]);
        vals[i] = v;
        local += v;
    }
    __shared__ float red[256];
    red[tt] = local;
    __syncthreads();
#pragma unroll
    for (int off = 128; off > 0; off >>= 1) {
        if (tt < off) red[tt] += red[tt + off];
        __syncthreads();
    }
    const float inv = 1.f / red[0];
#pragma unroll
    for (int i = 0; i < 8; i++)
        s[tt + i * 256] = vals[i] * inv;
}

extern "C" void kernel_launch(void* const* d_in, const int* in_sizes, int n_in,
                              void* d_out, int out_size)
{
    const float* q  = (const float*)d_in[0];
    const float* k  = (const float*)d_in[1];
    const float* v  = (const float*)d_in[2];
    const float* wq = (const float*)d_in[3];
    const float* wk = (const float*)d_in[4];
    const float* wv = (const float*)d_in[5];
    float* out = (float*)d_out;

    float *qp, *kp, *vp, *sbuf;
    cudaGetSymbolAddress((void**)&qp,   g_qp);
    cudaGetSymbolAddress((void**)&kp,   g_kp);
    cudaGetSymbolAddress((void**)&vp,   g_vp);
    cudaGetSymbolAddress((void**)&sbuf, g_s);

    const int SMEM_NT = (2 * ASZ + 2 * BM * ALD) * 4;   // 73728 B
    const int SMEM_NN = (2 * ASZ + 2 * BK * NLD) * 4;   // 70656 B
    cudaFuncSetAttribute(mma_gemm<true>,
                         cudaFuncAttributeMaxDynamicSharedMemorySize, SMEM_NT);
    cudaFuncSetAttribute(mma_gemm<false>,
                         cudaFuncAttributeMaxDynamicSharedMemorySize, SMEM_NN);

    const int MS = B_ * S_;
    const float inv_sqrt_d = 1.f / 32.f;

    // 1) Projections: xp = x @ W^T  (NT, M=8192, N=1024, K=1024)
    dim3 gproj(D_ / BN, MS / BM, 1);
    mma_gemm<true><<<gproj, 256, SMEM_NT>>>(q, wq, qp, MS, D_, D_, 0, 0, 0, 1.f);
    mma_gemm<true><<<gproj, 256, SMEM_NT>>>(k, wk, kp, MS, D_, D_, 0, 0, 0, 1.f);
    mma_gemm<true><<<gproj, 256, SMEM_NT>>>(v, wv, vp, MS, D_, D_, 0, 0, 0, 1.f);

    // 2) Scores: S = qp kp^T / 32  (batched NT, M=N=2048, K=1024)
    dim3 gsc(S_ / BN, S_ / BM, B_);
    mma_gemm<true><<<gsc, 256, SMEM_NT>>>(qp, kp, sbuf, S_, S_, D_,
                                          (size_t)S_ * D_, (size_t)S_ * D_,
                                          (size_t)S_ * S_, inv_sqrt_d);

    // 3) Softmax rows (in place)
    softmax_rows_kernel<<<B_ * S_, 256>>>(sbuf, S_);

    // 4) Output: out = P @ vp  (batched NN, M=2048, N=1024, K=2048)
    dim3 gout(D_ / BN, S_ / BM, B_);
    mma_gemm<false><<<gout, 256, SMEM_NN>>>(sbuf, vp, out, S_, D_, S_,
                                            (size_t)S_ * S_, (size_t)S_ * D_,
                                            (size_t)S_ * D_, 1.f);
}